// round 12
// baseline (speedup 1.0000x reference)
#include <cuda_runtime.h>
#include <cuda_bf16.h>
#include <math.h>

// Problem constants
#define S      2048
#define DIM    3072
#define NH     24
#define HD     128
#define QKVE   9216        // (24 + 24 + 24) * 128
#define EPSV   1e-6f
#define SCALE  0.08838834764831845f   // 1/sqrt(128)

// Scratch (module-load allocated, allowed)
__device__ float g_qkv[(size_t)S * QKVE];   // [S][9216]  q | k | v
__device__ float g_attn[(size_t)S * DIM];   // [S][3072]  attention output

// Packed fp32x2 FMA: d = a*b + d (lane-wise). sm_103a-only fast path.
__device__ __forceinline__ void ffma2(float2& d, const float2& a, const float2& b) {
    asm("fma.rn.f32x2 %0, %1, %2, %0;"
        : "+l"(reinterpret_cast<unsigned long long&>(d))
        : "l"(reinterpret_cast<const unsigned long long&>(a)),
          "l"(reinterpret_cast<const unsigned long long&>(b)));
}
// Broadcast one fp32 into both lanes of a packed pair (single mov.b64).
__device__ __forceinline__ float2 bcast2(float s) {
    float2 d;
    asm("mov.b64 %0, {%1, %1};"
        : "=l"(reinterpret_cast<unsigned long long&>(d)) : "f"(s));
    return d;
}

// ---------------------------------------------------------------------------
// GEMM:  C[M,N] = A[M,K] * B[N,K]^T   (both row-major, K contiguous: "NT")
// 128x128 tile, BK=16, 256 threads, 8x8 per-thread tile computed as f32x2
// packed FMAs. A tile stored DUPLICATED in smem (As[k][2c]=As[k][2c+1]=A[c])
// so (a,a) pairs come from one LDS.128. Register prefetch + double buffering.
// AS_STRIDE=260: multiple of 4 words so every LDS.128 stays 16B-aligned
// (258 trapped: odd k gave 8B-aligned float4 addresses), while 4*260 % 32 = 16
// still halves the A-store STS bank conflicts vs stride 256.
// CTA swizzle: group-major (GROUP_M=8, m-fastest) so 8 consecutive CTAs share
// one B tile -> B hits L2 instead of DRAM on the 113MB QKV weight.
// ---------------------------------------------------------------------------
#define GROUP_M   8
#define AS_STRIDE 260
#define BS_STRIDE 132
#define AS_WORDS  (16 * AS_STRIDE)                    // 4160 per buffer
#define BS_WORDS  (16 * BS_STRIDE)                    // 2112 per buffer
#define GEMM_SMEM_FLOATS (2 * AS_WORDS + 2 * BS_WORDS)
#define GEMM_SMEM_BYTES  (GEMM_SMEM_FLOATS * 4)       // 50,176

__global__ __launch_bounds__(256) void gemm_nt_kernel(
    const float* __restrict__ A, const float* __restrict__ B,
    float* __restrict__ C, int M, int N, int K)
{
    extern __shared__ float gsm[];
    float* const AsBuf0 = gsm;                         // [16][260]
    float* const AsBuf1 = gsm + AS_WORDS;
    float* const BsBuf0 = gsm + 2 * AS_WORDS;          // [16][132]
    float* const BsBuf1 = gsm + 2 * AS_WORDS + BS_WORDS;

    const int tid = threadIdx.x;
    const int ty  = tid >> 4;        // 0..15 -> row groups
    const int tx  = tid & 15;        // 0..15 -> col groups

    // Group-major CTA swizzle (m varies fastest within a GROUP_M-row group)
    const int num_pid_m = M >> 7;
    const int num_pid_n = N >> 7;
    const int pid = blockIdx.y * gridDim.x + blockIdx.x;
    const int num_pid_in_group = GROUP_M * num_pid_n;
    const int group_id = pid / num_pid_in_group;
    const int first_pid_m = group_id * GROUP_M;
    const int group_size_m = min(GROUP_M, num_pid_m - first_pid_m);
    const int pid_m = first_pid_m + (pid % group_size_m);
    const int pid_n = (pid % num_pid_in_group) / group_size_m;

    const int m0 = pid_m << 7;
    const int n0 = pid_n << 7;

    // Per-thread load coordinates: thread handles 2 (row, kquad) pairs
    const int r0  = tid >> 2;              // 0..63
    const int r1  = r0 + 64;               // 64..127
    const int kq  = tid & 3;               // float4 index within 16

    const float* Aptr0 = A + (size_t)(m0 + r0) * K + kq * 4;
    const float* Aptr1 = A + (size_t)(m0 + r1) * K + kq * 4;
    const float* Bptr0 = B + (size_t)(n0 + r0) * K + kq * 4;
    const float* Bptr1 = B + (size_t)(n0 + r1) * K + kq * 4;

    float2 acc[8][4];
#pragma unroll
    for (int i = 0; i < 8; i++)
#pragma unroll
        for (int j = 0; j < 4; j++) acc[i][j] = make_float2(0.f, 0.f);

    // Prologue: fetch first tile into regs, store into buffer 0
    float4 va0 = *(const float4*)(Aptr0);
    float4 va1 = *(const float4*)(Aptr1);
    float4 vb0 = *(const float4*)(Bptr0);
    float4 vb1 = *(const float4*)(Bptr1);

#pragma unroll
    for (int q = 0; q < 4; q++) {
        const float a0 = (&va0.x)[q], a1 = (&va1.x)[q];
        const int row = kq * 4 + q;
        *(float2*)&AsBuf0[row * AS_STRIDE + 2 * r0] = make_float2(a0, a0);
        *(float2*)&AsBuf0[row * AS_STRIDE + 2 * r1] = make_float2(a1, a1);
        BsBuf0[row * BS_STRIDE + r0] = (&vb0.x)[q];
        BsBuf0[row * BS_STRIDE + r1] = (&vb1.x)[q];
    }
    __syncthreads();

    const int T = K / 16;
    for (int t = 0; t < T; t++) {
        const float* As = (t & 1) ? AsBuf1 : AsBuf0;
        const float* Bs = (t & 1) ? BsBuf1 : BsBuf0;

        // Prefetch next tile into registers (overlaps the FMA loop)
        if (t + 1 < T) {
            const int koff = (t + 1) * 16;
            va0 = *(const float4*)(Aptr0 + koff);
            va1 = *(const float4*)(Aptr1 + koff);
            vb0 = *(const float4*)(Bptr0 + koff);
            vb1 = *(const float4*)(Bptr1 + koff);
        }

#pragma unroll
        for (int k = 0; k < 16; k++) {
            // A pairs (duplicated): rows {ty*4+i} at words 8ty+2i,
            //                       rows {64+ty*4+i} at 128+8ty+2i. Broadcast.
            float4 a01 = *(const float4*)&As[k * AS_STRIDE + ty * 8];
            float4 a23 = *(const float4*)&As[k * AS_STRIDE + ty * 8 + 4];
            float4 a45 = *(const float4*)&As[k * AS_STRIDE + 128 + ty * 8];
            float4 a67 = *(const float4*)&As[k * AS_STRIDE + 128 + ty * 8 + 4];
            // B pairs: cols {tx*4..}, {64+tx*4..}.
            float4 b03 = *(const float4*)&Bs[k * BS_STRIDE + tx * 4];
            float4 b47 = *(const float4*)&Bs[k * BS_STRIDE + 64 + tx * 4];

            const float2* pa0 = reinterpret_cast<const float2*>(&a01);
            const float2* pa2 = reinterpret_cast<const float2*>(&a23);
            const float2* pa4 = reinterpret_cast<const float2*>(&a45);
            const float2* pa6 = reinterpret_cast<const float2*>(&a67);
            const float2* pb0 = reinterpret_cast<const float2*>(&b03);
            const float2* pb4 = reinterpret_cast<const float2*>(&b47);

            const float2 pa[8] = { pa0[0], pa0[1], pa2[0], pa2[1],
                                   pa4[0], pa4[1], pa6[0], pa6[1] };
#pragma unroll
            for (int i = 0; i < 8; i++) {
                ffma2(acc[i][0], pa[i], pb0[0]);
                ffma2(acc[i][1], pa[i], pb0[1]);
                ffma2(acc[i][2], pa[i], pb4[0]);
                ffma2(acc[i][3], pa[i], pb4[1]);
            }
        }

        // Store prefetched tile into the other buffer; single barrier.
        if (t + 1 < T) {
            float* Asn = (t & 1) ? AsBuf0 : AsBuf1;
            float* Bsn = (t & 1) ? BsBuf0 : BsBuf1;
#pragma unroll
            for (int q = 0; q < 4; q++) {
                const float a0 = (&va0.x)[q], a1 = (&va1.x)[q];
                const int row = kq * 4 + q;
                *(float2*)&Asn[row * AS_STRIDE + 2 * r0] = make_float2(a0, a0);
                *(float2*)&Asn[row * AS_STRIDE + 2 * r1] = make_float2(a1, a1);
                Bsn[row * BS_STRIDE + r0] = (&vb0.x)[q];
                Bsn[row * BS_STRIDE + r1] = (&vb1.x)[q];
            }
            __syncthreads();
        }
    }

    // Epilogue: rows {ty*4+i, 64+ty*4+i}, cols {tx*4, 64+tx*4}
#pragma unroll
    for (int half = 0; half < 2; half++) {
#pragma unroll
        for (int i = 0; i < 4; i++) {
            const int r = m0 + half * 64 + ty * 4 + i;
            float* crow = C + (size_t)r * N + n0;
            const int ai = half * 4 + i;
            *(float4*)(crow + tx * 4)      = make_float4(acc[ai][0].x, acc[ai][0].y,
                                                          acc[ai][1].x, acc[ai][1].y);
            *(float4*)(crow + 64 + tx * 4) = make_float4(acc[ai][2].x, acc[ai][2].y,
                                                          acc[ai][3].x, acc[ai][3].y);
        }
    }
}

// ---------------------------------------------------------------------------
// Fused RMSNorm (per head, 128 dims) + interleaved RoPE, in place on g_qkv.
// One WARP per head: lane owns 4 dims = exactly 2 complete interleaved RoPE
// pairs, so no smem / no block barriers. Shuffle reduction for sum-of-squares.
// grid = (12, S): blockIdx.x*4+warp = head slot (0..23 Q, 24..47 K).
// ---------------------------------------------------------------------------
__global__ __launch_bounds__(128) void normrope_kernel(
    float* __restrict__ qkv,
    const float* __restrict__ cosb, const float* __restrict__ sinb,
    const float* __restrict__ wq,   const float* __restrict__ wk)
{
    const int s    = blockIdx.y;
    const int hi   = blockIdx.x * 4 + (threadIdx.x >> 5);  // 0..47
    const int lane = threadIdx.x & 31;

    float* base = qkv + (size_t)s * QKVE +
                  (hi < NH ? hi * HD : DIM + (hi - NH) * HD);
    const float* w = (hi < NH) ? wq : wk;

    float4 x = *(const float4*)(base + lane * 4);

    float ss = x.x * x.x + x.y * x.y + x.z * x.z + x.w * x.w;
#pragma unroll
    for (int o = 16; o > 0; o >>= 1) ss += __shfl_xor_sync(0xffffffffu, ss, o);
    const float inv = rsqrtf(ss * (1.0f / 128.0f) + EPSV);

    const float4 wv = *(const float4*)(w + lane * 4);
    x.x *= inv * wv.x;  x.y *= inv * wv.y;
    x.z *= inv * wv.z;  x.w *= inv * wv.w;

    // RoPE pairs p = 2*lane (elements x,y) and p+1 (elements z,w)
    const float2 c2 = *(const float2*)(cosb + (size_t)s * 64 + lane * 2);
    const float2 s2 = *(const float2*)(sinb + (size_t)s * 64 + lane * 2);
    float4 o;
    o.x = x.x * c2.x - x.y * s2.x;
    o.y = x.y * c2.x + x.x * s2.x;
    o.z = x.z * c2.y - x.w * s2.y;
    o.w = x.w * c2.y + x.z * s2.y;
    *(float4*)(base + lane * 4) = o;
}

// ---------------------------------------------------------------------------
// Flash attention: per (q-block of 64, head). BN=64 keys per tile, D=128.
// 256 threads, 2 CTAs/SM (97.75 KB smem). QK and PV loops run on packed
// f32x2 FMAs. K rows read as j*16+tx, V cols split {tx*4, 64+tx*4}:
// all hot LDS phases conflict-free.
// P aliases the Ks region (K dead after score pass; barrier-protected).
// attention_mask is all-ones by construction -> masking is a no-op (dropped).
// ---------------------------------------------------------------------------
#define K_STRIDE  132
#define QV_STRIDE 128
#define P_STRIDE  68
// Layout: Qs [64][128] | Ks [64][132] (P [64][68] aliases) | Vs [64][128] | m/l/c
#define FL_OFF_Q  0
#define FL_OFF_K  (64 * QV_STRIDE)
#define FL_OFF_V  (FL_OFF_K + 64 * K_STRIDE)
#define FL_OFF_R  (FL_OFF_V + 64 * QV_STRIDE)
#define FL_SMEM_FLOATS (FL_OFF_R + 3 * 64)
#define FL_SMEM_BYTES  (FL_SMEM_FLOATS * 4)

__global__ __launch_bounds__(256, 2) void flash_kernel(
    const float* __restrict__ qkv,
    float* __restrict__ out)
{
    extern __shared__ float sm[];
    float* Qs   = sm + FL_OFF_Q;              // [64][128]
    float* Ks   = sm + FL_OFF_K;              // [64][132]
    float* Vs   = sm + FL_OFF_V;              // [64][128]
    float* P    = sm + FL_OFF_K;              // [64][68], aliases Ks
    float* mrow = sm + FL_OFF_R;              // [64]
    float* lrow = mrow + 64;                  // [64]
    float* crow = lrow + 64;                  // [64]

    const int tid = threadIdx.x;
    const int ty  = tid >> 4;                 // 0..15 -> 4 rows each
    const int tx  = tid & 15;                 // 0..15
    const int h   = blockIdx.y;
    const int q0  = blockIdx.x * 64;

    // Softmax role: 4 threads per row; lane-adjacent threads share a row.
    const int srow = tid >> 2;                // 0..63
    const int sseg = tid & 3;                 // 0..3 -> 16 columns each

    // Load Q tile [64][128]
    {
        const float* qbase = qkv + (size_t)q0 * QKVE + h * HD;
        for (int i = tid; i < 64 * 32; i += 256) {
            int r  = i >> 5;                 // row 0..63
            int d4 = i & 31;                 // float4 index 0..31
            float4 v = *(const float4*)(qbase + (size_t)r * QKVE + d4 * 4);
            *(float4*)&Qs[r * QV_STRIDE + d4 * 4] = v;
        }
    }
    if (tid < 64) { mrow[tid] = -3.0e38f; lrow[tid] = 0.f; }

    // O accumulator: 4 rows x 4 packed col-pairs (cols {tx*4, 64+tx*4})
    float2 acc[4][4];
#pragma unroll
    for (int i = 0; i < 4; i++)
#pragma unroll
        for (int j = 0; j < 4; j++) acc[i][j] = make_float2(0.f, 0.f);

    for (int kt = 0; kt < S / 64; kt++) {
        const int k0 = kt * 64;
        const float* kbase = qkv + (size_t)k0 * QKVE + DIM + h * HD;
        const float* vbase = kbase + DIM;

        __syncthreads();   // prev tile's P/Vs fully consumed; Qs init visible
        for (int i = tid; i < 64 * 32; i += 256) {
            int r  = i >> 5;
            int d4 = i & 31;
            float4 kv = *(const float4*)(kbase + (size_t)r * QKVE + d4 * 4);
            *(float4*)&Ks[r * K_STRIDE + d4 * 4] = kv;
            float4 vv = *(const float4*)(vbase + (size_t)r * QKVE + d4 * 4);
            *(float4*)&Vs[r * QV_STRIDE + d4 * 4] = vv;
        }
        __syncthreads();

        // Scores via packed pairs along d: sc2[i][j] accumulates lane-wise,
        // collapsed after the loop. K rows j*16+tx: conflict-free.
        float2 sc2[4][4];
#pragma unroll
        for (int i = 0; i < 4; i++)
#pragma unroll
            for (int j = 0; j < 4; j++) sc2[i][j] = make_float2(0.f, 0.f);

#pragma unroll 4
        for (int d4 = 0; d4 < 32; d4++) {
            float4 qa[4], kb[4];
#pragma unroll
            for (int i = 0; i < 4; i++)
                qa[i] = *(const float4*)&Qs[(ty * 4 + i) * QV_STRIDE + d4 * 4];
#pragma unroll
            for (int j = 0; j < 4; j++)
                kb[j] = *(const float4*)&Ks[(j * 16 + tx) * K_STRIDE + d4 * 4];
#pragma unroll
            for (int i = 0; i < 4; i++) {
                const float2* qp = reinterpret_cast<const float2*>(&qa[i]);
#pragma unroll
                for (int j = 0; j < 4; j++) {
                    const float2* kp = reinterpret_cast<const float2*>(&kb[j]);
                    ffma2(sc2[i][j], qp[0], kp[0]);
                    ffma2(sc2[i][j], qp[1], kp[1]);
                }
            }
        }
        __syncthreads();   // all K reads done before P (aliasing Ks) is written

        // Collapse lanes, scale, store to P at col = j*16+tx (conflict-free)
#pragma unroll
        for (int i = 0; i < 4; i++) {
            float* prow = &P[(ty * 4 + i) * P_STRIDE];
#pragma unroll
            for (int j = 0; j < 4; j++)
                prow[j * 16 + tx] = (sc2[i][j].x + sc2[i][j].y) * SCALE;
        }
        __syncthreads();

        // Online softmax, all threads: 4 threads per row, 16 cols each.
        {
            const int cbase = sseg * 16;
            float mx = -3.0e38f;
            float4 p0 = *(const float4*)&P[srow * P_STRIDE + cbase + 0];
            float4 p1 = *(const float4*)&P[srow * P_STRIDE + cbase + 4];
            float4 p2 = *(const float4*)&P[srow * P_STRIDE + cbase + 8];
            float4 p3 = *(const float4*)&P[srow * P_STRIDE + cbase + 12];
            mx = fmaxf(mx, fmaxf(fmaxf(p0.x, p0.y), fmaxf(p0.z, p0.w)));
            mx = fmaxf(mx, fmaxf(fmaxf(p1.x, p1.y), fmaxf(p1.z, p1.w)));
            mx = fmaxf(mx, fmaxf(fmaxf(p2.x, p2.y), fmaxf(p2.z, p2.w)));
            mx = fmaxf(mx, fmaxf(fmaxf(p3.x, p3.y), fmaxf(p3.z, p3.w)));
            // combine across the 4 row-threads (lanes differ in bits 0..1)
            mx = fmaxf(mx, __shfl_xor_sync(0xffffffffu, mx, 1));
            mx = fmaxf(mx, __shfl_xor_sync(0xffffffffu, mx, 2));
            float mold = mrow[srow];
            mx = fmaxf(mx, mold);

            float ssum;
            {
                p0.x = __expf(p0.x - mx); p0.y = __expf(p0.y - mx);
                p0.z = __expf(p0.z - mx); p0.w = __expf(p0.w - mx);
                p1.x = __expf(p1.x - mx); p1.y = __expf(p1.y - mx);
                p1.z = __expf(p1.z - mx); p1.w = __expf(p1.w - mx);
                p2.x = __expf(p2.x - mx); p2.y = __expf(p2.y - mx);
                p2.z = __expf(p2.z - mx); p2.w = __expf(p2.w - mx);
                p3.x = __expf(p3.x - mx); p3.y = __expf(p3.y - mx);
                p3.z = __expf(p3.z - mx); p3.w = __expf(p3.w - mx);
                *(float4*)&P[srow * P_STRIDE + cbase + 0]  = p0;
                *(float4*)&P[srow * P_STRIDE + cbase + 4]  = p1;
                *(float4*)&P[srow * P_STRIDE + cbase + 8]  = p2;
                *(float4*)&P[srow * P_STRIDE + cbase + 12] = p3;
                ssum = (p0.x + p0.y + p0.z + p0.w) + (p1.x + p1.y + p1.z + p1.w)
                     + (p2.x + p2.y + p2.z + p2.w) + (p3.x + p3.y + p3.z + p3.w);
            }
            ssum += __shfl_xor_sync(0xffffffffu, ssum, 1);
            ssum += __shfl_xor_sync(0xffffffffu, ssum, 2);

            if (sseg == 0) {
                float c = __expf(mold - mx);
                lrow[srow] = lrow[srow] * c + ssum;
                mrow[srow] = mx;
                crow[srow] = c;
            }
        }
        __syncthreads();

        // O = O*corr + P @ V on packed pairs (V cols {tx*4, 64+tx*4})
#pragma unroll
        for (int i = 0; i < 4; i++) {
            const float c = crow[ty * 4 + i];
#pragma unroll
            for (int j = 0; j < 4; j++) { acc[i][j].x *= c; acc[i][j].y *= c; }
        }

#pragma unroll 4
        for (int j = 0; j < 64; j++) {
            float2 pv2[4];
#pragma unroll
            for (int i = 0; i < 4; i++)
                pv2[i] = bcast2(P[(ty * 4 + i) * P_STRIDE + j]);
            float4 v0 = *(const float4*)&Vs[j * QV_STRIDE + tx * 4];
            float4 v1 = *(const float4*)&Vs[j * QV_STRIDE + 64 + tx * 4];
            const float2* vp0 = reinterpret_cast<const float2*>(&v0);
            const float2* vp1 = reinterpret_cast<const float2*>(&v1);
#pragma unroll
            for (int i = 0; i < 4; i++) {
                ffma2(acc[i][0], pv2[i], vp0[0]);
                ffma2(acc[i][1], pv2[i], vp0[1]);
                ffma2(acc[i][2], pv2[i], vp1[0]);
                ffma2(acc[i][3], pv2[i], vp1[1]);
            }
        }
    }

    // Epilogue: normalize and write cols {tx*4, 64+tx*4} of [s][h*128 + d]
#pragma unroll
    for (int i = 0; i < 4; i++) {
        float linv = 1.0f / lrow[ty * 4 + i];
        float* orow = out + (size_t)(q0 + ty * 4 + i) * DIM + h * HD;
        *(float4*)(orow + tx * 4)      = make_float4(acc[i][0].x * linv, acc[i][0].y * linv,
                                                      acc[i][1].x * linv, acc[i][1].y * linv);
        *(float4*)(orow + 64 + tx * 4) = make_float4(acc[i][2].x * linv, acc[i][2].y * linv,
                                                      acc[i][3].x * linv, acc[i][3].y * linv);
    }
}

// ---------------------------------------------------------------------------
extern "C" void kernel_launch(void* const* d_in, const int* in_sizes, int n_in,
                              void* d_out, int out_size)
{
    const float* hidden = (const float*)d_in[0];
    // d_in[1] = attention_mask: all-ones by construction, unused.
    const float* cosb   = (const float*)d_in[2];
    const float* sinb   = (const float*)d_in[3];
    const float* w_qkv  = (const float*)d_in[4];
    const float* wq     = (const float*)d_in[5];
    const float* wk     = (const float*)d_in[6];
    const float* w_out  = (const float*)d_in[7];
    float* out = (float*)d_out;

    float *qkv, *attn;
    cudaGetSymbolAddress((void**)&qkv,  g_qkv);
    cudaGetSymbolAddress((void**)&attn, g_attn);

    cudaFuncSetAttribute(gemm_nt_kernel, cudaFuncAttributeMaxDynamicSharedMemorySize,
                         GEMM_SMEM_BYTES);
    cudaFuncSetAttribute(flash_kernel, cudaFuncAttributeMaxDynamicSharedMemorySize,
                         FL_SMEM_BYTES);

    // 1. QKV projection: [2048,3072] x [9216,3072]^T -> [2048,9216]
    gemm_nt_kernel<<<dim3(QKVE / 128, S / 128), 256, GEMM_SMEM_BYTES>>>(
        hidden, w_qkv, qkv, S, QKVE, DIM);

    // 2. RMSNorm + RoPE on Q and K heads (in place); 1 warp per head
    normrope_kernel<<<dim3(12, S), 128>>>(qkv, cosb, sinb, wq, wk);

    // 3. Attention
    flash_kernel<<<dim3(S / 64, NH), 256, FL_SMEM_BYTES>>>(qkv, attn);

    // 4. Output projection: [2048,3072] x [3072,3072]^T -> [2048,3072]
    gemm_nt_kernel<<<dim3(DIM / 128, S / 128), 256, GEMM_SMEM_BYTES>>>(
        attn, w_out, out, S, DIM, DIM);
}

// round 14
// speedup vs baseline: 1.1316x; 1.1316x over previous
#include <cuda_runtime.h>
#include <cuda_bf16.h>
#include <math.h>

// Problem constants
#define S      2048
#define DIM    3072
#define NH     24
#define HD     128
#define QKVE   9216        // (24 + 24 + 24) * 128
#define EPSV   1e-6f
#define SCALE  0.08838834764831845f   // 1/sqrt(128)

// Scratch (module-load allocated, allowed)
__device__ float g_qkv[(size_t)S * QKVE];   // [S][9216]  q | k | v
__device__ float g_attn[(size_t)S * DIM];   // [S][3072]  attention output

// Packed fp32x2 FMA: d = a*b + d (lane-wise). sm_103a-only fast path.
__device__ __forceinline__ void ffma2(float2& d, const float2& a, const float2& b) {
    asm("fma.rn.f32x2 %0, %1, %2, %0;"
        : "+l"(reinterpret_cast<unsigned long long&>(d))
        : "l"(reinterpret_cast<const unsigned long long&>(a)),
          "l"(reinterpret_cast<const unsigned long long&>(b)));
}
// Broadcast one fp32 into both lanes of a packed pair (single mov.b64).
__device__ __forceinline__ float2 bcast2(float s) {
    float2 d;
    asm("mov.b64 %0, {%1, %1};"
        : "=l"(reinterpret_cast<unsigned long long&>(d)) : "f"(s));
    return d;
}

// ---------------------------------------------------------------------------
// GEMM:  C[M,N] = A[M,K] * B[N,K]^T   (both row-major, K contiguous: "NT")
// 128x128 tile, BK=16, 256 threads, 8x8 per-thread tile computed as f32x2
// packed FMAs. A tile stored DUPLICATED in smem (As[k][2c]=As[k][2c+1]=A[c])
// so (a,a) pairs come from one LDS.128. Register prefetch + double buffering.
// __launch_bounds__(256, 2): cap regs at 128 -> 2 CTAs/SM (R12 ncu: 146 regs
// forced 1 CTA/SM, occ 12.5%, issue 33.9%, fma 42.3% -> latency-bound).
// AS_STRIDE=260: multiple of 4 words so every LDS.128 stays 16B-aligned.
// CTA swizzle: group-major (GROUP_M=8) so 8 consecutive CTAs share one B tile.
// ---------------------------------------------------------------------------
#define GROUP_M   8
#define AS_STRIDE 260
#define BS_STRIDE 132
#define AS_WORDS  (16 * AS_STRIDE)                    // 4160 per buffer
#define BS_WORDS  (16 * BS_STRIDE)                    // 2112 per buffer
#define GEMM_SMEM_FLOATS (2 * AS_WORDS + 2 * BS_WORDS)
#define GEMM_SMEM_BYTES  (GEMM_SMEM_FLOATS * 4)       // 50,176

__global__ __launch_bounds__(256, 2) void gemm_nt_kernel(
    const float* __restrict__ A, const float* __restrict__ B,
    float* __restrict__ C, int M, int N, int K)
{
    extern __shared__ float gsm[];
    float* const AsBuf0 = gsm;                         // [16][260]
    float* const AsBuf1 = gsm + AS_WORDS;
    float* const BsBuf0 = gsm + 2 * AS_WORDS;          // [16][132]
    float* const BsBuf1 = gsm + 2 * AS_WORDS + BS_WORDS;

    const int tid = threadIdx.x;
    const int ty  = tid >> 4;        // 0..15 -> row groups
    const int tx  = tid & 15;        // 0..15 -> col groups

    // Group-major CTA swizzle (m varies fastest within a GROUP_M-row group)
    const int num_pid_m = M >> 7;
    const int num_pid_n = N >> 7;
    const int pid = blockIdx.y * gridDim.x + blockIdx.x;
    const int num_pid_in_group = GROUP_M * num_pid_n;
    const int group_id = pid / num_pid_in_group;
    const int first_pid_m = group_id * GROUP_M;
    const int group_size_m = min(GROUP_M, num_pid_m - first_pid_m);
    const int pid_m = first_pid_m + (pid % group_size_m);
    const int pid_n = (pid % num_pid_in_group) / group_size_m;

    const int m0 = pid_m << 7;
    const int n0 = pid_n << 7;

    // Per-thread load coordinates: thread handles 2 (row, kquad) pairs
    const int r0  = tid >> 2;              // 0..63
    const int r1  = r0 + 64;               // 64..127
    const int kq  = tid & 3;               // float4 index within 16

    const float* Aptr0 = A + (size_t)(m0 + r0) * K + kq * 4;
    const float* Aptr1 = A + (size_t)(m0 + r1) * K + kq * 4;
    const float* Bptr0 = B + (size_t)(n0 + r0) * K + kq * 4;
    const float* Bptr1 = B + (size_t)(n0 + r1) * K + kq * 4;

    float2 acc[8][4];
#pragma unroll
    for (int i = 0; i < 8; i++)
#pragma unroll
        for (int j = 0; j < 4; j++) acc[i][j] = make_float2(0.f, 0.f);

    // Prologue: fetch first tile into regs, store into buffer 0
    float4 va0 = *(const float4*)(Aptr0);
    float4 va1 = *(const float4*)(Aptr1);
    float4 vb0 = *(const float4*)(Bptr0);
    float4 vb1 = *(const float4*)(Bptr1);

#pragma unroll
    for (int q = 0; q < 4; q++) {
        const float a0 = (&va0.x)[q], a1 = (&va1.x)[q];
        const int row = kq * 4 + q;
        *(float2*)&AsBuf0[row * AS_STRIDE + 2 * r0] = make_float2(a0, a0);
        *(float2*)&AsBuf0[row * AS_STRIDE + 2 * r1] = make_float2(a1, a1);
        BsBuf0[row * BS_STRIDE + r0] = (&vb0.x)[q];
        BsBuf0[row * BS_STRIDE + r1] = (&vb1.x)[q];
    }
    __syncthreads();

    const int T = K / 16;
    for (int t = 0; t < T; t++) {
        const float* As = (t & 1) ? AsBuf1 : AsBuf0;
        const float* Bs = (t & 1) ? BsBuf1 : BsBuf0;

        // Prefetch next tile into registers (overlaps the FMA loop)
        if (t + 1 < T) {
            const int koff = (t + 1) * 16;
            va0 = *(const float4*)(Aptr0 + koff);
            va1 = *(const float4*)(Aptr1 + koff);
            vb0 = *(const float4*)(Bptr0 + koff);
            vb1 = *(const float4*)(Bptr1 + koff);
        }

#pragma unroll
        for (int k = 0; k < 16; k++) {
            // A pairs (duplicated): rows {ty*4+i} at words 8ty+2i,
            //                       rows {64+ty*4+i} at 128+8ty+2i. Broadcast.
            float4 a01 = *(const float4*)&As[k * AS_STRIDE + ty * 8];
            float4 a23 = *(const float4*)&As[k * AS_STRIDE + ty * 8 + 4];
            float4 a45 = *(const float4*)&As[k * AS_STRIDE + 128 + ty * 8];
            float4 a67 = *(const float4*)&As[k * AS_STRIDE + 128 + ty * 8 + 4];
            // B pairs: cols {tx*4..}, {64+tx*4..}.
            float4 b03 = *(const float4*)&Bs[k * BS_STRIDE + tx * 4];
            float4 b47 = *(const float4*)&Bs[k * BS_STRIDE + 64 + tx * 4];

            const float2* pa0 = reinterpret_cast<const float2*>(&a01);
            const float2* pa2 = reinterpret_cast<const float2*>(&a23);
            const float2* pa4 = reinterpret_cast<const float2*>(&a45);
            const float2* pa6 = reinterpret_cast<const float2*>(&a67);
            const float2* pb0 = reinterpret_cast<const float2*>(&b03);
            const float2* pb4 = reinterpret_cast<const float2*>(&b47);

#pragma unroll
            for (int h2 = 0; h2 < 2; h2++) {
                const float2* pa = (h2 == 0) ? pa0 : pa4;
                const float2* pc = (h2 == 0) ? pa2 : pa6;
#pragma unroll
                for (int u = 0; u < 2; u++) {
                    const int i = h2 * 4 + u;
                    ffma2(acc[i][0], pa[u], pb0[0]);
                    ffma2(acc[i][1], pa[u], pb0[1]);
                    ffma2(acc[i][2], pa[u], pb4[0]);
                    ffma2(acc[i][3], pa[u], pb4[1]);
                }
#pragma unroll
                for (int u = 0; u < 2; u++) {
                    const int i = h2 * 4 + 2 + u;
                    ffma2(acc[i][0], pc[u], pb0[0]);
                    ffma2(acc[i][1], pc[u], pb0[1]);
                    ffma2(acc[i][2], pc[u], pb4[0]);
                    ffma2(acc[i][3], pc[u], pb4[1]);
                }
            }
        }

        // Store prefetched tile into the other buffer; single barrier.
        if (t + 1 < T) {
            float* Asn = (t & 1) ? AsBuf0 : AsBuf1;
            float* Bsn = (t & 1) ? BsBuf0 : BsBuf1;
#pragma unroll
            for (int q = 0; q < 4; q++) {
                const float a0 = (&va0.x)[q], a1 = (&va1.x)[q];
                const int row = kq * 4 + q;
                *(float2*)&Asn[row * AS_STRIDE + 2 * r0] = make_float2(a0, a0);
                *(float2*)&Asn[row * AS_STRIDE + 2 * r1] = make_float2(a1, a1);
                Bsn[row * BS_STRIDE + r0] = (&vb0.x)[q];
                Bsn[row * BS_STRIDE + r1] = (&vb1.x)[q];
            }
            __syncthreads();
        }
    }

    // Epilogue: rows {ty*4+i, 64+ty*4+i}, cols {tx*4, 64+tx*4}
#pragma unroll
    for (int half = 0; half < 2; half++) {
#pragma unroll
        for (int i = 0; i < 4; i++) {
            const int r = m0 + half * 64 + ty * 4 + i;
            float* crow = C + (size_t)r * N + n0;
            const int ai = half * 4 + i;
            *(float4*)(crow + tx * 4)      = make_float4(acc[ai][0].x, acc[ai][0].y,
                                                          acc[ai][1].x, acc[ai][1].y);
            *(float4*)(crow + 64 + tx * 4) = make_float4(acc[ai][2].x, acc[ai][2].y,
                                                          acc[ai][3].x, acc[ai][3].y);
        }
    }
}

// ---------------------------------------------------------------------------
// Fused RMSNorm (per head, 128 dims) + interleaved RoPE, in place on g_qkv.
// One WARP per head: lane owns 4 dims = exactly 2 complete interleaved RoPE
// pairs, so no smem / no block barriers. Shuffle reduction for sum-of-squares.
// grid = (12, S): blockIdx.x*4+warp = head slot (0..23 Q, 24..47 K).
// ---------------------------------------------------------------------------
__global__ __launch_bounds__(128) void normrope_kernel(
    float* __restrict__ qkv,
    const float* __restrict__ cosb, const float* __restrict__ sinb,
    const float* __restrict__ wq,   const float* __restrict__ wk)
{
    const int s    = blockIdx.y;
    const int hi   = blockIdx.x * 4 + (threadIdx.x >> 5);  // 0..47
    const int lane = threadIdx.x & 31;

    float* base = qkv + (size_t)s * QKVE +
                  (hi < NH ? hi * HD : DIM + (hi - NH) * HD);
    const float* w = (hi < NH) ? wq : wk;

    float4 x = *(const float4*)(base + lane * 4);

    float ss = x.x * x.x + x.y * x.y + x.z * x.z + x.w * x.w;
#pragma unroll
    for (int o = 16; o > 0; o >>= 1) ss += __shfl_xor_sync(0xffffffffu, ss, o);
    const float inv = rsqrtf(ss * (1.0f / 128.0f) + EPSV);

    const float4 wv = *(const float4*)(w + lane * 4);
    x.x *= inv * wv.x;  x.y *= inv * wv.y;
    x.z *= inv * wv.z;  x.w *= inv * wv.w;

    // RoPE pairs p = 2*lane (elements x,y) and p+1 (elements z,w)
    const float2 c2 = *(const float2*)(cosb + (size_t)s * 64 + lane * 2);
    const float2 s2 = *(const float2*)(sinb + (size_t)s * 64 + lane * 2);
    float4 o;
    o.x = x.x * c2.x - x.y * s2.x;
    o.y = x.y * c2.x + x.x * s2.x;
    o.z = x.z * c2.y - x.w * s2.y;
    o.w = x.w * c2.y + x.z * s2.y;
    *(float4*)(base + lane * 4) = o;
}

// ---------------------------------------------------------------------------
// Flash attention: per (q-block of 64, head). BN=64 keys per tile, D=128.
// 256 threads, 2 CTAs/SM (97.75 KB smem). QK and PV loops run on packed
// f32x2 FMAs. K rows read as j*16+tx, V cols split {tx*4, 64+tx*4}:
// all hot LDS phases conflict-free.
// P aliases the Ks region (K dead after score pass; barrier-protected).
// attention_mask is all-ones by construction -> masking is a no-op (dropped).
// ---------------------------------------------------------------------------
#define K_STRIDE  132
#define QV_STRIDE 128
#define P_STRIDE  68
// Layout: Qs [64][128] | Ks [64][132] (P [64][68] aliases) | Vs [64][128] | m/l/c
#define FL_OFF_Q  0
#define FL_OFF_K  (64 * QV_STRIDE)
#define FL_OFF_V  (FL_OFF_K + 64 * K_STRIDE)
#define FL_OFF_R  (FL_OFF_V + 64 * QV_STRIDE)
#define FL_SMEM_FLOATS (FL_OFF_R + 3 * 64)
#define FL_SMEM_BYTES  (FL_SMEM_FLOATS * 4)

__global__ __launch_bounds__(256, 2) void flash_kernel(
    const float* __restrict__ qkv,
    float* __restrict__ out)
{
    extern __shared__ float sm[];
    float* Qs   = sm + FL_OFF_Q;              // [64][128]
    float* Ks   = sm + FL_OFF_K;              // [64][132]
    float* Vs   = sm + FL_OFF_V;              // [64][128]
    float* P    = sm + FL_OFF_K;              // [64][68], aliases Ks
    float* mrow = sm + FL_OFF_R;              // [64]
    float* lrow = mrow + 64;                  // [64]
    float* crow = lrow + 64;                  // [64]

    const int tid = threadIdx.x;
    const int ty  = tid >> 4;                 // 0..15 -> 4 rows each
    const int tx  = tid & 15;                 // 0..15
    const int h   = blockIdx.y;
    const int q0  = blockIdx.x * 64;

    // Softmax role: 4 threads per row; lane-adjacent threads share a row.
    const int srow = tid >> 2;                // 0..63
    const int sseg = tid & 3;                 // 0..3 -> 16 columns each

    // Load Q tile [64][128]
    {
        const float* qbase = qkv + (size_t)q0 * QKVE + h * HD;
        for (int i = tid; i < 64 * 32; i += 256) {
            int r  = i >> 5;                 // row 0..63
            int d4 = i & 31;                 // float4 index 0..31
            float4 v = *(const float4*)(qbase + (size_t)r * QKVE + d4 * 4);
            *(float4*)&Qs[r * QV_STRIDE + d4 * 4] = v;
        }
    }
    if (tid < 64) { mrow[tid] = -3.0e38f; lrow[tid] = 0.f; }

    // O accumulator: 4 rows x 4 packed col-pairs (cols {tx*4, 64+tx*4})
    float2 acc[4][4];
#pragma unroll
    for (int i = 0; i < 4; i++)
#pragma unroll
        for (int j = 0; j < 4; j++) acc[i][j] = make_float2(0.f, 0.f);

    for (int kt = 0; kt < S / 64; kt++) {
        const int k0 = kt * 64;
        const float* kbase = qkv + (size_t)k0 * QKVE + DIM + h * HD;
        const float* vbase = kbase + DIM;

        __syncthreads();   // prev tile's P/Vs fully consumed; Qs init visible
        for (int i = tid; i < 64 * 32; i += 256) {
            int r  = i >> 5;
            int d4 = i & 31;
            float4 kv = *(const float4*)(kbase + (size_t)r * QKVE + d4 * 4);
            *(float4*)&Ks[r * K_STRIDE + d4 * 4] = kv;
            float4 vv = *(const float4*)(vbase + (size_t)r * QKVE + d4 * 4);
            *(float4*)&Vs[r * QV_STRIDE + d4 * 4] = vv;
        }
        __syncthreads();

        // Scores via packed pairs along d: sc2[i][j] accumulates lane-wise,
        // collapsed after the loop. K rows j*16+tx: conflict-free.
        float2 sc2[4][4];
#pragma unroll
        for (int i = 0; i < 4; i++)
#pragma unroll
            for (int j = 0; j < 4; j++) sc2[i][j] = make_float2(0.f, 0.f);

#pragma unroll 4
        for (int d4 = 0; d4 < 32; d4++) {
            float4 qa[4], kb[4];
#pragma unroll
            for (int i = 0; i < 4; i++)
                qa[i] = *(const float4*)&Qs[(ty * 4 + i) * QV_STRIDE + d4 * 4];
#pragma unroll
            for (int j = 0; j < 4; j++)
                kb[j] = *(const float4*)&Ks[(j * 16 + tx) * K_STRIDE + d4 * 4];
#pragma unroll
            for (int i = 0; i < 4; i++) {
                const float2* qp = reinterpret_cast<const float2*>(&qa[i]);
#pragma unroll
                for (int j = 0; j < 4; j++) {
                    const float2* kp = reinterpret_cast<const float2*>(&kb[j]);
                    ffma2(sc2[i][j], qp[0], kp[0]);
                    ffma2(sc2[i][j], qp[1], kp[1]);
                }
            }
        }
        __syncthreads();   // all K reads done before P (aliasing Ks) is written

        // Collapse lanes, scale, store to P at col = j*16+tx (conflict-free)
#pragma unroll
        for (int i = 0; i < 4; i++) {
            float* prow = &P[(ty * 4 + i) * P_STRIDE];
#pragma unroll
            for (int j = 0; j < 4; j++)
                prow[j * 16 + tx] = (sc2[i][j].x + sc2[i][j].y) * SCALE;
        }
        __syncthreads();

        // Online softmax, all threads: 4 threads per row, 16 cols each.
        {
            const int cbase = sseg * 16;
            float mx = -3.0e38f;
            float4 p0 = *(const float4*)&P[srow * P_STRIDE + cbase + 0];
            float4 p1 = *(const float4*)&P[srow * P_STRIDE + cbase + 4];
            float4 p2 = *(const float4*)&P[srow * P_STRIDE + cbase + 8];
            float4 p3 = *(const float4*)&P[srow * P_STRIDE + cbase + 12];
            mx = fmaxf(mx, fmaxf(fmaxf(p0.x, p0.y), fmaxf(p0.z, p0.w)));
            mx = fmaxf(mx, fmaxf(fmaxf(p1.x, p1.y), fmaxf(p1.z, p1.w)));
            mx = fmaxf(mx, fmaxf(fmaxf(p2.x, p2.y), fmaxf(p2.z, p2.w)));
            mx = fmaxf(mx, fmaxf(fmaxf(p3.x, p3.y), fmaxf(p3.z, p3.w)));
            // combine across the 4 row-threads (lanes differ in bits 0..1)
            mx = fmaxf(mx, __shfl_xor_sync(0xffffffffu, mx, 1));
            mx = fmaxf(mx, __shfl_xor_sync(0xffffffffu, mx, 2));
            float mold = mrow[srow];
            mx = fmaxf(mx, mold);

            float ssum;
            {
                p0.x = __expf(p0.x - mx); p0.y = __expf(p0.y - mx);
                p0.z = __expf(p0.z - mx); p0.w = __expf(p0.w - mx);
                p1.x = __expf(p1.x - mx); p1.y = __expf(p1.y - mx);
                p1.z = __expf(p1.z - mx); p1.w = __expf(p1.w - mx);
                p2.x = __expf(p2.x - mx); p2.y = __expf(p2.y - mx);
                p2.z = __expf(p2.z - mx); p2.w = __expf(p2.w - mx);
                p3.x = __expf(p3.x - mx); p3.y = __expf(p3.y - mx);
                p3.z = __expf(p3.z - mx); p3.w = __expf(p3.w - mx);
                *(float4*)&P[srow * P_STRIDE + cbase + 0]  = p0;
                *(float4*)&P[srow * P_STRIDE + cbase + 4]  = p1;
                *(float4*)&P[srow * P_STRIDE + cbase + 8]  = p2;
                *(float4*)&P[srow * P_STRIDE + cbase + 12] = p3;
                ssum = (p0.x + p0.y + p0.z + p0.w) + (p1.x + p1.y + p1.z + p1.w)
                     + (p2.x + p2.y + p2.z + p2.w) + (p3.x + p3.y + p3.z + p3.w);
            }
            ssum += __shfl_xor_sync(0xffffffffu, ssum, 1);
            ssum += __shfl_xor_sync(0xffffffffu, ssum, 2);

            if (sseg == 0) {
                float c = __expf(mold - mx);
                lrow[srow] = lrow[srow] * c + ssum;
                mrow[srow] = mx;
                crow[srow] = c;
            }
        }
        __syncthreads();

        // O = O*corr + P @ V on packed pairs (V cols {tx*4, 64+tx*4})
#pragma unroll
        for (int i = 0; i < 4; i++) {
            const float c = crow[ty * 4 + i];
#pragma unroll
            for (int j = 0; j < 4; j++) { acc[i][j].x *= c; acc[i][j].y *= c; }
        }

#pragma unroll 4
        for (int j = 0; j < 64; j++) {
            float2 pv2[4];
#pragma unroll
            for (int i = 0; i < 4; i++)
                pv2[i] = bcast2(P[(ty * 4 + i) * P_STRIDE + j]);
            float4 v0 = *(const float4*)&Vs[j * QV_STRIDE + tx * 4];
            float4 v1 = *(const float4*)&Vs[j * QV_STRIDE + 64 + tx * 4];
            const float2* vp0 = reinterpret_cast<const float2*>(&v0);
            const float2* vp1 = reinterpret_cast<const float2*>(&v1);
#pragma unroll
            for (int i = 0; i < 4; i++) {
                ffma2(acc[i][0], pv2[i], vp0[0]);
                ffma2(acc[i][1], pv2[i], vp0[1]);
                ffma2(acc[i][2], pv2[i], vp1[0]);
                ffma2(acc[i][3], pv2[i], vp1[1]);
            }
        }
    }

    // Epilogue: normalize and write cols {tx*4, 64+tx*4} of [s][h*128 + d]
#pragma unroll
    for (int i = 0; i < 4; i++) {
        float linv = 1.0f / lrow[ty * 4 + i];
        float* orow = out + (size_t)(q0 + ty * 4 + i) * DIM + h * HD;
        *(float4*)(orow + tx * 4)      = make_float4(acc[i][0].x * linv, acc[i][0].y * linv,
                                                      acc[i][1].x * linv, acc[i][1].y * linv);
        *(float4*)(orow + 64 + tx * 4) = make_float4(acc[i][2].x * linv, acc[i][2].y * linv,
                                                      acc[i][3].x * linv, acc[i][3].y * linv);
    }
}

// ---------------------------------------------------------------------------
extern "C" void kernel_launch(void* const* d_in, const int* in_sizes, int n_in,
                              void* d_out, int out_size)
{
    const float* hidden = (const float*)d_in[0];
    // d_in[1] = attention_mask: all-ones by construction, unused.
    const float* cosb   = (const float*)d_in[2];
    const float* sinb   = (const float*)d_in[3];
    const float* w_qkv  = (const float*)d_in[4];
    const float* wq     = (const float*)d_in[5];
    const float* wk     = (const float*)d_in[6];
    const float* w_out  = (const float*)d_in[7];
    float* out = (float*)d_out;

    float *qkv, *attn;
    cudaGetSymbolAddress((void**)&qkv,  g_qkv);
    cudaGetSymbolAddress((void**)&attn, g_attn);

    cudaFuncSetAttribute(gemm_nt_kernel, cudaFuncAttributeMaxDynamicSharedMemorySize,
                         GEMM_SMEM_BYTES);
    cudaFuncSetAttribute(flash_kernel, cudaFuncAttributeMaxDynamicSharedMemorySize,
                         FL_SMEM_BYTES);

    // 1. QKV projection: [2048,3072] x [9216,3072]^T -> [2048,9216]
    gemm_nt_kernel<<<dim3(QKVE / 128, S / 128), 256, GEMM_SMEM_BYTES>>>(
        hidden, w_qkv, qkv, S, QKVE, DIM);

    // 2. RMSNorm + RoPE on Q and K heads (in place); 1 warp per head
    normrope_kernel<<<dim3(12, S), 128>>>(qkv, cosb, sinb, wq, wk);

    // 3. Attention
    flash_kernel<<<dim3(S / 64, NH), 256, FL_SMEM_BYTES>>>(qkv, attn);

    // 4. Output projection: [2048,3072] x [3072,3072]^T -> [2048,3072]
    gemm_nt_kernel<<<dim3(DIM / 128, S / 128), 256, GEMM_SMEM_BYTES>>>(
        attn, w_out, out, S, DIM, DIM);
}

// round 17
// speedup vs baseline: 1.3561x; 1.1984x over previous
#include <cuda_runtime.h>
#include <cuda_bf16.h>
#include <math.h>

// Problem constants
#define S      2048
#define DIM    3072
#define NH     24
#define HD     128
#define QKVE   9216        // (24 + 24 + 24) * 128
#define EPSV   1e-6f
#define SCALE  0.08838834764831845f   // 1/sqrt(128)

// Scratch (module-load allocated, allowed)
__device__ float g_qkv[(size_t)S * QKVE];   // [S][9216]  q | k | v
__device__ float g_attn[(size_t)S * DIM];   // [S][3072]  attention output

// Packed fp32x2 FMA: d = a*b + d (lane-wise). sm_103a-only fast path.
__device__ __forceinline__ void ffma2(float2& d, const float2& a, const float2& b) {
    asm("fma.rn.f32x2 %0, %1, %2, %0;"
        : "+l"(reinterpret_cast<unsigned long long&>(d))
        : "l"(reinterpret_cast<const unsigned long long&>(a)),
          "l"(reinterpret_cast<const unsigned long long&>(b)));
}
// Broadcast one fp32 into both lanes of a packed pair (single mov.b64).
__device__ __forceinline__ float2 bcast2(float s) {
    float2 d;
    asm("mov.b64 %0, {%1, %1};"
        : "=l"(reinterpret_cast<unsigned long long&>(d)) : "f"(s));
    return d;
}

// ---------------------------------------------------------------------------
// GEMM:  C[M,N] = A[M,K] * B[N,K]^T   (both row-major, K contiguous: "NT")
// 128x128 tile, BK=16, 256 threads, 8x8 per-thread tile computed as f32x2
// packed FMAs. R14 ncu: L1 72.1% / fma 48.5% -> crossbar-bound from the
// DUPLICATED A tile. Now A stored plain ([16][132]); the (a,a) packed pairs
// are built with mov.b64 broadcasts on the idle ALU pipe. LDS bytes per
// thread-k: 96 -> 64. Register prefetch + double buffering; one barrier/tile.
// __launch_bounds__(256, 2): 128 regs -> 2 CTAs/SM.
// Strides 132 (= 0 mod 4 words): LDS.128 16B-aligned (258 trapped earlier).
// CTA swizzle: group-major (GROUP_M=8) so 8 consecutive CTAs share one B tile.
// ---------------------------------------------------------------------------
#define GROUP_M   8
#define TS_STRIDE 132
#define TS_WORDS  (16 * TS_STRIDE)                    // 2112 per buffer
#define GEMM_SMEM_FLOATS (4 * TS_WORDS)               // A0,A1,B0,B1
#define GEMM_SMEM_BYTES  (GEMM_SMEM_FLOATS * 4)       // 33,792

__global__ __launch_bounds__(256, 2) void gemm_nt_kernel(
    const float* __restrict__ A, const float* __restrict__ B,
    float* __restrict__ C, int M, int N, int K)
{
    extern __shared__ float gsm[];
    float* const AsBuf0 = gsm;                         // [16][132]
    float* const AsBuf1 = gsm + TS_WORDS;
    float* const BsBuf0 = gsm + 2 * TS_WORDS;          // [16][132]
    float* const BsBuf1 = gsm + 3 * TS_WORDS;

    const int tid = threadIdx.x;
    const int ty  = tid >> 4;        // 0..15 -> row groups
    const int tx  = tid & 15;        // 0..15 -> col groups

    // Group-major CTA swizzle (m varies fastest within a GROUP_M-row group)
    const int num_pid_m = M >> 7;
    const int num_pid_n = N >> 7;
    const int pid = blockIdx.y * gridDim.x + blockIdx.x;
    const int num_pid_in_group = GROUP_M * num_pid_n;
    const int group_id = pid / num_pid_in_group;
    const int first_pid_m = group_id * GROUP_M;
    const int group_size_m = min(GROUP_M, num_pid_m - first_pid_m);
    const int pid_m = first_pid_m + (pid % group_size_m);
    const int pid_n = (pid % num_pid_in_group) / group_size_m;

    const int m0 = pid_m << 7;
    const int n0 = pid_n << 7;

    // Per-thread load coordinates: thread handles 2 (row, kquad) pairs
    const int r0  = tid >> 2;              // 0..63
    const int r1  = r0 + 64;               // 64..127
    const int kq  = tid & 3;               // float4 index within 16

    const float* Aptr0 = A + (size_t)(m0 + r0) * K + kq * 4;
    const float* Aptr1 = A + (size_t)(m0 + r1) * K + kq * 4;
    const float* Bptr0 = B + (size_t)(n0 + r0) * K + kq * 4;
    const float* Bptr1 = B + (size_t)(n0 + r1) * K + kq * 4;

    float2 acc[8][4];
#pragma unroll
    for (int i = 0; i < 8; i++)
#pragma unroll
        for (int j = 0; j < 4; j++) acc[i][j] = make_float2(0.f, 0.f);

    // Prologue: fetch first tile into regs, store into buffer 0
    float4 va0 = *(const float4*)(Aptr0);
    float4 va1 = *(const float4*)(Aptr1);
    float4 vb0 = *(const float4*)(Bptr0);
    float4 vb1 = *(const float4*)(Bptr1);

#pragma unroll
    for (int q = 0; q < 4; q++) {
        const int row = kq * 4 + q;
        AsBuf0[row * TS_STRIDE + r0] = (&va0.x)[q];
        AsBuf0[row * TS_STRIDE + r1] = (&va1.x)[q];
        BsBuf0[row * TS_STRIDE + r0] = (&vb0.x)[q];
        BsBuf0[row * TS_STRIDE + r1] = (&vb1.x)[q];
    }
    __syncthreads();

    const int T = K / 16;
    for (int t = 0; t < T; t++) {
        const float* As = (t & 1) ? AsBuf1 : AsBuf0;
        const float* Bs = (t & 1) ? BsBuf1 : BsBuf0;

        // Prefetch next tile into registers (overlaps the FMA loop)
        if (t + 1 < T) {
            const int koff = (t + 1) * 16;
            va0 = *(const float4*)(Aptr0 + koff);
            va1 = *(const float4*)(Aptr1 + koff);
            vb0 = *(const float4*)(Bptr0 + koff);
            vb1 = *(const float4*)(Bptr1 + koff);
        }

#pragma unroll
        for (int k = 0; k < 16; k++) {
            // A: rows {ty*4..ty*4+3} and {64+ty*4..}; broadcast across tx.
            float4 a03 = *(const float4*)&As[k * TS_STRIDE + ty * 4];
            float4 a47 = *(const float4*)&As[k * TS_STRIDE + 64 + ty * 4];
            // B: cols {tx*4..}, {64+tx*4..}; conflict-free across lanes.
            float4 b03 = *(const float4*)&Bs[k * TS_STRIDE + tx * 4];
            float4 b47 = *(const float4*)&Bs[k * TS_STRIDE + 64 + tx * 4];

            const float2* pb0 = reinterpret_cast<const float2*>(&b03);
            const float2* pb4 = reinterpret_cast<const float2*>(&b47);

#pragma unroll
            for (int h2 = 0; h2 < 2; h2++) {
                const float4& av = (h2 == 0) ? a03 : a47;
                float2 p0 = bcast2(av.x);
                float2 p1 = bcast2(av.y);
                float2 p2 = bcast2(av.z);
                float2 p3 = bcast2(av.w);
                const int ib = h2 * 4;
                ffma2(acc[ib + 0][0], p0, pb0[0]);
                ffma2(acc[ib + 0][1], p0, pb0[1]);
                ffma2(acc[ib + 0][2], p0, pb4[0]);
                ffma2(acc[ib + 0][3], p0, pb4[1]);
                ffma2(acc[ib + 1][0], p1, pb0[0]);
                ffma2(acc[ib + 1][1], p1, pb0[1]);
                ffma2(acc[ib + 1][2], p1, pb4[0]);
                ffma2(acc[ib + 1][3], p1, pb4[1]);
                ffma2(acc[ib + 2][0], p2, pb0[0]);
                ffma2(acc[ib + 2][1], p2, pb0[1]);
                ffma2(acc[ib + 2][2], p2, pb4[0]);
                ffma2(acc[ib + 2][3], p2, pb4[1]);
                ffma2(acc[ib + 3][0], p3, pb0[0]);
                ffma2(acc[ib + 3][1], p3, pb0[1]);
                ffma2(acc[ib + 3][2], p3, pb4[0]);
                ffma2(acc[ib + 3][3], p3, pb4[1]);
            }
        }

        // Store prefetched tile into the other buffer; single barrier.
        if (t + 1 < T) {
            float* Asn = (t & 1) ? AsBuf0 : AsBuf1;
            float* Bsn = (t & 1) ? BsBuf0 : BsBuf1;
#pragma unroll
            for (int q = 0; q < 4; q++) {
                const int row = kq * 4 + q;
                Asn[row * TS_STRIDE + r0] = (&va0.x)[q];
                Asn[row * TS_STRIDE + r1] = (&va1.x)[q];
                Bsn[row * TS_STRIDE + r0] = (&vb0.x)[q];
                Bsn[row * TS_STRIDE + r1] = (&vb1.x)[q];
            }
            __syncthreads();
        }
    }

    // Epilogue: rows {ty*4+i, 64+ty*4+i}, cols {tx*4, 64+tx*4}
#pragma unroll
    for (int half = 0; half < 2; half++) {
#pragma unroll
        for (int i = 0; i < 4; i++) {
            const int r = m0 + half * 64 + ty * 4 + i;
            float* crow = C + (size_t)r * N + n0;
            const int ai = half * 4 + i;
            *(float4*)(crow + tx * 4)      = make_float4(acc[ai][0].x, acc[ai][0].y,
                                                          acc[ai][1].x, acc[ai][1].y);
            *(float4*)(crow + 64 + tx * 4) = make_float4(acc[ai][2].x, acc[ai][2].y,
                                                          acc[ai][3].x, acc[ai][3].y);
        }
    }
}

// ---------------------------------------------------------------------------
// Fused RMSNorm (per head, 128 dims) + interleaved RoPE, in place on g_qkv.
// One WARP per head: lane owns 4 dims = exactly 2 complete interleaved RoPE
// pairs, so no smem / no block barriers. Shuffle reduction for sum-of-squares.
// grid = (12, S): blockIdx.x*4+warp = head slot (0..23 Q, 24..47 K).
// ---------------------------------------------------------------------------
__global__ __launch_bounds__(128) void normrope_kernel(
    float* __restrict__ qkv,
    const float* __restrict__ cosb, const float* __restrict__ sinb,
    const float* __restrict__ wq,   const float* __restrict__ wk)
{
    const int s    = blockIdx.y;
    const int hi   = blockIdx.x * 4 + (threadIdx.x >> 5);  // 0..47
    const int lane = threadIdx.x & 31;

    float* base = qkv + (size_t)s * QKVE +
                  (hi < NH ? hi * HD : DIM + (hi - NH) * HD);
    const float* w = (hi < NH) ? wq : wk;

    float4 x = *(const float4*)(base + lane * 4);

    float ss = x.x * x.x + x.y * x.y + x.z * x.z + x.w * x.w;
#pragma unroll
    for (int o = 16; o > 0; o >>= 1) ss += __shfl_xor_sync(0xffffffffu, ss, o);
    const float inv = rsqrtf(ss * (1.0f / 128.0f) + EPSV);

    const float4 wv = *(const float4*)(w + lane * 4);
    x.x *= inv * wv.x;  x.y *= inv * wv.y;
    x.z *= inv * wv.z;  x.w *= inv * wv.w;

    // RoPE pairs p = 2*lane (elements x,y) and p+1 (elements z,w)
    const float2 c2 = *(const float2*)(cosb + (size_t)s * 64 + lane * 2);
    const float2 s2 = *(const float2*)(sinb + (size_t)s * 64 + lane * 2);
    float4 o;
    o.x = x.x * c2.x - x.y * s2.x;
    o.y = x.y * c2.x + x.x * s2.x;
    o.z = x.z * c2.y - x.w * s2.y;
    o.w = x.w * c2.y + x.z * s2.y;
    *(float4*)(base + lane * 4) = o;
}

// ---------------------------------------------------------------------------
// Flash attention: per (q-block of 64, head). BN=64 keys per tile, D=128.
// 256 threads, 2 CTAs/SM (97.75 KB smem). QK and PV loops run on packed
// f32x2 FMAs. K rows read as j*16+tx, V cols split {tx*4, 64+tx*4}:
// all hot LDS phases conflict-free.
// P aliases the Ks region (K dead after score pass; barrier-protected).
// attention_mask is all-ones by construction -> masking is a no-op (dropped).
// ---------------------------------------------------------------------------
#define K_STRIDE  132
#define QV_STRIDE 128
#define P_STRIDE  68
// Layout: Qs [64][128] | Ks [64][132] (P [64][68] aliases) | Vs [64][128] | m/l/c
#define FL_OFF_Q  0
#define FL_OFF_K  (64 * QV_STRIDE)
#define FL_OFF_V  (FL_OFF_K + 64 * K_STRIDE)
#define FL_OFF_R  (FL_OFF_V + 64 * QV_STRIDE)
#define FL_SMEM_FLOATS (FL_OFF_R + 3 * 64)
#define FL_SMEM_BYTES  (FL_SMEM_FLOATS * 4)

__global__ __launch_bounds__(256, 2) void flash_kernel(
    const float* __restrict__ qkv,
    float* __restrict__ out)
{
    extern __shared__ float sm[];
    float* Qs   = sm + FL_OFF_Q;              // [64][128]
    float* Ks   = sm + FL_OFF_K;              // [64][132]
    float* Vs   = sm + FL_OFF_V;              // [64][128]
    float* P    = sm + FL_OFF_K;              // [64][68], aliases Ks
    float* mrow = sm + FL_OFF_R;              // [64]
    float* lrow = mrow + 64;                  // [64]
    float* crow = lrow + 64;                  // [64]

    const int tid = threadIdx.x;
    const int ty  = tid >> 4;                 // 0..15 -> 4 rows each
    const int tx  = tid & 15;                 // 0..15
    const int h   = blockIdx.y;
    const int q0  = blockIdx.x * 64;

    // Softmax role: 4 threads per row; lane-adjacent threads share a row.
    const int srow = tid >> 2;                // 0..63
    const int sseg = tid & 3;                 // 0..3 -> 16 columns each

    // Load Q tile [64][128]
    {
        const float* qbase = qkv + (size_t)q0 * QKVE + h * HD;
        for (int i = tid; i < 64 * 32; i += 256) {
            int r  = i >> 5;                 // row 0..63
            int d4 = i & 31;                 // float4 index 0..31
            float4 v = *(const float4*)(qbase + (size_t)r * QKVE + d4 * 4);
            *(float4*)&Qs[r * QV_STRIDE + d4 * 4] = v;
        }
    }
    if (tid < 64) { mrow[tid] = -3.0e38f; lrow[tid] = 0.f; }

    // O accumulator: 4 rows x 4 packed col-pairs (cols {tx*4, 64+tx*4})
    float2 acc[4][4];
#pragma unroll
    for (int i = 0; i < 4; i++)
#pragma unroll
        for (int j = 0; j < 4; j++) acc[i][j] = make_float2(0.f, 0.f);

    for (int kt = 0; kt < S / 64; kt++) {
        const int k0 = kt * 64;
        const float* kbase = qkv + (size_t)k0 * QKVE + DIM + h * HD;
        const float* vbase = kbase + DIM;

        __syncthreads();   // prev tile's P/Vs fully consumed; Qs init visible
        for (int i = tid; i < 64 * 32; i += 256) {
            int r  = i >> 5;
            int d4 = i & 31;
            float4 kv = *(const float4*)(kbase + (size_t)r * QKVE + d4 * 4);
            *(float4*)&Ks[r * K_STRIDE + d4 * 4] = kv;
            float4 vv = *(const float4*)(vbase + (size_t)r * QKVE + d4 * 4);
            *(float4*)&Vs[r * QV_STRIDE + d4 * 4] = vv;
        }
        __syncthreads();

        // Scores via packed pairs along d: sc2[i][j] accumulates lane-wise,
        // collapsed after the loop. K rows j*16+tx: conflict-free.
        float2 sc2[4][4];
#pragma unroll
        for (int i = 0; i < 4; i++)
#pragma unroll
            for (int j = 0; j < 4; j++) sc2[i][j] = make_float2(0.f, 0.f);

#pragma unroll 4
        for (int d4 = 0; d4 < 32; d4++) {
            float4 qa[4], kb[4];
#pragma unroll
            for (int i = 0; i < 4; i++)
                qa[i] = *(const float4*)&Qs[(ty * 4 + i) * QV_STRIDE + d4 * 4];
#pragma unroll
            for (int j = 0; j < 4; j++)
                kb[j] = *(const float4*)&Ks[(j * 16 + tx) * K_STRIDE + d4 * 4];
#pragma unroll
            for (int i = 0; i < 4; i++) {
                const float2* qp = reinterpret_cast<const float2*>(&qa[i]);
#pragma unroll
                for (int j = 0; j < 4; j++) {
                    const float2* kp = reinterpret_cast<const float2*>(&kb[j]);
                    ffma2(sc2[i][j], qp[0], kp[0]);
                    ffma2(sc2[i][j], qp[1], kp[1]);
                }
            }
        }
        __syncthreads();   // all K reads done before P (aliasing Ks) is written

        // Collapse lanes, scale, store to P at col = j*16+tx (conflict-free)
#pragma unroll
        for (int i = 0; i < 4; i++) {
            float* prow = &P[(ty * 4 + i) * P_STRIDE];
#pragma unroll
            for (int j = 0; j < 4; j++)
                prow[j * 16 + tx] = (sc2[i][j].x + sc2[i][j].y) * SCALE;
        }
        __syncthreads();

        // Online softmax, all threads: 4 threads per row, 16 cols each.
        {
            const int cbase = sseg * 16;
            float mx = -3.0e38f;
            float4 p0 = *(const float4*)&P[srow * P_STRIDE + cbase + 0];
            float4 p1 = *(const float4*)&P[srow * P_STRIDE + cbase + 4];
            float4 p2 = *(const float4*)&P[srow * P_STRIDE + cbase + 8];
            float4 p3 = *(const float4*)&P[srow * P_STRIDE + cbase + 12];
            mx = fmaxf(mx, fmaxf(fmaxf(p0.x, p0.y), fmaxf(p0.z, p0.w)));
            mx = fmaxf(mx, fmaxf(fmaxf(p1.x, p1.y), fmaxf(p1.z, p1.w)));
            mx = fmaxf(mx, fmaxf(fmaxf(p2.x, p2.y), fmaxf(p2.z, p2.w)));
            mx = fmaxf(mx, fmaxf(fmaxf(p3.x, p3.y), fmaxf(p3.z, p3.w)));
            // combine across the 4 row-threads (lanes differ in bits 0..1)
            mx = fmaxf(mx, __shfl_xor_sync(0xffffffffu, mx, 1));
            mx = fmaxf(mx, __shfl_xor_sync(0xffffffffu, mx, 2));
            float mold = mrow[srow];
            mx = fmaxf(mx, mold);

            float ssum;
            {
                p0.x = __expf(p0.x - mx); p0.y = __expf(p0.y - mx);
                p0.z = __expf(p0.z - mx); p0.w = __expf(p0.w - mx);
                p1.x = __expf(p1.x - mx); p1.y = __expf(p1.y - mx);
                p1.z = __expf(p1.z - mx); p1.w = __expf(p1.w - mx);
                p2.x = __expf(p2.x - mx); p2.y = __expf(p2.y - mx);
                p2.z = __expf(p2.z - mx); p2.w = __expf(p2.w - mx);
                p3.x = __expf(p3.x - mx); p3.y = __expf(p3.y - mx);
                p3.z = __expf(p3.z - mx); p3.w = __expf(p3.w - mx);
                *(float4*)&P[srow * P_STRIDE + cbase + 0]  = p0;
                *(float4*)&P[srow * P_STRIDE + cbase + 4]  = p1;
                *(float4*)&P[srow * P_STRIDE + cbase + 8]  = p2;
                *(float4*)&P[srow * P_STRIDE + cbase + 12] = p3;
                ssum = (p0.x + p0.y + p0.z + p0.w) + (p1.x + p1.y + p1.z + p1.w)
                     + (p2.x + p2.y + p2.z + p2.w) + (p3.x + p3.y + p3.z + p3.w);
            }
            ssum += __shfl_xor_sync(0xffffffffu, ssum, 1);
            ssum += __shfl_xor_sync(0xffffffffu, ssum, 2);

            if (sseg == 0) {
                float c = __expf(mold - mx);
                lrow[srow] = lrow[srow] * c + ssum;
                mrow[srow] = mx;
                crow[srow] = c;
            }
        }
        __syncthreads();

        // O = O*corr + P @ V on packed pairs (V cols {tx*4, 64+tx*4})
#pragma unroll
        for (int i = 0; i < 4; i++) {
            const float c = crow[ty * 4 + i];
#pragma unroll
            for (int j = 0; j < 4; j++) { acc[i][j].x *= c; acc[i][j].y *= c; }
        }

#pragma unroll 4
        for (int j = 0; j < 64; j++) {
            float2 pv2[4];
#pragma unroll
            for (int i = 0; i < 4; i++)
                pv2[i] = bcast2(P[(ty * 4 + i) * P_STRIDE + j]);
            float4 v0 = *(const float4*)&Vs[j * QV_STRIDE + tx * 4];
            float4 v1 = *(const float4*)&Vs[j * QV_STRIDE + 64 + tx * 4];
            const float2* vp0 = reinterpret_cast<const float2*>(&v0);
            const float2* vp1 = reinterpret_cast<const float2*>(&v1);
#pragma unroll
            for (int i = 0; i < 4; i++) {
                ffma2(acc[i][0], pv2[i], vp0[0]);
                ffma2(acc[i][1], pv2[i], vp0[1]);
                ffma2(acc[i][2], pv2[i], vp1[0]);
                ffma2(acc[i][3], pv2[i], vp1[1]);
            }
        }
    }

    // Epilogue: normalize and write cols {tx*4, 64+tx*4} of [s][h*128 + d]
#pragma unroll
    for (int i = 0; i < 4; i++) {
        float linv = 1.0f / lrow[ty * 4 + i];
        float* orow = out + (size_t)(q0 + ty * 4 + i) * DIM + h * HD;
        *(float4*)(orow + tx * 4)      = make_float4(acc[i][0].x * linv, acc[i][0].y * linv,
                                                      acc[i][1].x * linv, acc[i][1].y * linv);
        *(float4*)(orow + 64 + tx * 4) = make_float4(acc[i][2].x * linv, acc[i][2].y * linv,
                                                      acc[i][3].x * linv, acc[i][3].y * linv);
    }
}

// ---------------------------------------------------------------------------
extern "C" void kernel_launch(void* const* d_in, const int* in_sizes, int n_in,
                              void* d_out, int out_size)
{
    const float* hidden = (const float*)d_in[0];
    // d_in[1] = attention_mask: all-ones by construction, unused.
    const float* cosb   = (const float*)d_in[2];
    const float* sinb   = (const float*)d_in[3];
    const float* w_qkv  = (const float*)d_in[4];
    const float* wq     = (const float*)d_in[5];
    const float* wk     = (const float*)d_in[6];
    const float* w_out  = (const float*)d_in[7];
    float* out = (float*)d_out;

    float *qkv, *attn;
    cudaGetSymbolAddress((void**)&qkv,  g_qkv);
    cudaGetSymbolAddress((void**)&attn, g_attn);

    cudaFuncSetAttribute(gemm_nt_kernel, cudaFuncAttributeMaxDynamicSharedMemorySize,
                         GEMM_SMEM_BYTES);
    cudaFuncSetAttribute(flash_kernel, cudaFuncAttributeMaxDynamicSharedMemorySize,
                         FL_SMEM_BYTES);

    // 1. QKV projection: [2048,3072] x [9216,3072]^T -> [2048,9216]
    gemm_nt_kernel<<<dim3(QKVE / 128, S / 128), 256, GEMM_SMEM_BYTES>>>(
        hidden, w_qkv, qkv, S, QKVE, DIM);

    // 2. RMSNorm + RoPE on Q and K heads (in place); 1 warp per head
    normrope_kernel<<<dim3(12, S), 128>>>(qkv, cosb, sinb, wq, wk);

    // 3. Attention
    flash_kernel<<<dim3(S / 64, NH), 256, FL_SMEM_BYTES>>>(qkv, attn);

    // 4. Output projection: [2048,3072] x [3072,3072]^T -> [2048,3072]
    gemm_nt_kernel<<<dim3(DIM / 128, S / 128), 256, GEMM_SMEM_BYTES>>>(
        attn, w_out, out, S, DIM, DIM);
}